// round 1
// baseline (speedup 1.0000x reference)
#include <cuda_runtime.h>
#include <math.h>

// ---------------------------------------------------------------------------
// HanningTemplateLayer == single 80-tap FIR:
//   out[b,j] = sum_{t=0..79} c[t] * x[b, j+t-40]   (zero padded)
//   c[t]     = sum_w softmax(tw)_w * hann_{2w}[(t-40)+w],  w in {10,20,30,40}
// ---------------------------------------------------------------------------

#define THREADS 128
#define VOUT    16                 // outputs per thread (per row)
#define TILE    (THREADS * VOUT)   // 2048 columns per block
#define TAPS    80
#define HALF    40
#define SWZPAD  32                 // swizzle can bump index by up to 15

__device__ float2 g_c2[TAPS];      // combined filter, duplicated (c,c)

// XOR swizzle: keeps per-thread 128B-strided window reads conflict-free.
__device__ __forceinline__ int swz(int i) { return i ^ ((i >> 4) & 15); }

__global__ void build_coeffs_kernel(const float* __restrict__ tw) {
    int t = threadIdx.x;
    // softmax over 4 template weights (redundant per thread, trivial)
    float w0 = tw[0], w1 = tw[1], w2 = tw[2], w3 = tw[3];
    float m  = fmaxf(fmaxf(w0, w1), fmaxf(w2, w3));
    float e0 = expf(w0 - m), e1 = expf(w1 - m), e2 = expf(w2 - m), e3 = expf(w3 - m);
    float s  = e0 + e1 + e2 + e3;
    float p[4] = { e0 / s, e1 / s, e2 / s, e3 / s };
    const int widths[4] = { 10, 20, 30, 40 };

    if (t < TAPS) {
        int d = t - HALF;                       // d in [-40, 39]
        double acc = 0.0;
        #pragma unroll
        for (int i = 0; i < 4; ++i) {
            int w = widths[i];
            int k = d + w;                      // index into hanning(2w)
            if (k >= 0 && k < 2 * w) {
                // np.hanning(M)[k] = 0.5 - 0.5*cos(2*pi*k/(M-1)), M = 2w (f64 then cast)
                double h = 0.5 - 0.5 * cos(2.0 * M_PI * (double)k / (double)(2 * w - 1));
                acc += (double)p[i] * h;
            }
        }
        float c = (float)acc;
        g_c2[t] = make_float2(c, c);
    }
}

__global__ __launch_bounds__(THREADS)
void fir80_kernel(const float* __restrict__ x, float* __restrict__ out, int L) {
    __shared__ __align__(16) float2 sx[TILE + TAPS + SWZPAD]; // interleaved row pair
    __shared__ __align__(16) float2 sc[TAPS];

    const int rp   = blockIdx.y;            // row pair index (2 rows per block)
    const int col0 = blockIdx.x * TILE;     // first output column of this block
    const float* __restrict__ xa = x + (size_t)(2 * rp)     * L;
    const float* __restrict__ xb = x + (size_t)(2 * rp + 1) * L;

    // Cooperative tile load: shared index i <-> global column col0 - 40 + i
    for (int i = threadIdx.x; i < TILE + TAPS; i += THREADS) {
        int g = col0 - HALF + i;
        float a = 0.0f, b = 0.0f;
        if (g >= 0 && g < L) { a = xa[g]; b = xb[g]; }
        sx[swz(i)] = make_float2(a, b);
    }
    if (threadIdx.x < TAPS) sc[threadIdx.x] = g_c2[threadIdx.x];
    __syncthreads();

    const unsigned long long* __restrict__ su =
        reinterpret_cast<const unsigned long long*>(sx);
    const unsigned long long* __restrict__ cu =
        reinterpret_cast<const unsigned long long*>(sc);

    const int lo = threadIdx.x * VOUT;      // shared index of (j0 - 40)

    unsigned long long acc[VOUT];
    unsigned long long win[VOUT];
    #pragma unroll
    for (int v = 0; v < VOUT; ++v) acc[v] = 0ull;
    #pragma unroll
    for (int v = 0; v < VOUT; ++v) win[v] = su[swz(lo + v)];

    // Invariant at tap t: win[(t+i) & (VOUT-1)] holds sx[lo + t + i], i in [0,VOUT)
    #pragma unroll
    for (int t = 0; t < TAPS; ++t) {
        unsigned long long c2 = cu[t];
        #pragma unroll
        for (int v = 0; v < VOUT; ++v) {
            asm("fma.rn.f32x2 %0, %1, %2, %0;"
                : "+l"(acc[v])
                : "l"(win[(t + v) & (VOUT - 1)]), "l"(c2));
        }
        if (t < TAPS - 1)
            win[t & (VOUT - 1)] = su[swz(lo + t + VOUT)];
    }

    // Unpack and store: 16 consecutive floats per row -> 4x float4 per row
    float ra[VOUT], rb[VOUT];
    #pragma unroll
    for (int v = 0; v < VOUT; ++v) {
        float2 r;
        asm("mov.b64 {%0, %1}, %2;" : "=f"(r.x), "=f"(r.y) : "l"(acc[v]));
        ra[v] = r.x; rb[v] = r.y;
    }
    float* oa = out + (size_t)(2 * rp)     * L + col0 + lo;
    float* ob = out + (size_t)(2 * rp + 1) * L + col0 + lo;
    #pragma unroll
    for (int v = 0; v < VOUT; v += 4) {
        *reinterpret_cast<float4*>(oa + v) = make_float4(ra[v], ra[v+1], ra[v+2], ra[v+3]);
        *reinterpret_cast<float4*>(ob + v) = make_float4(rb[v], rb[v+1], rb[v+2], rb[v+3]);
    }
}

extern "C" void kernel_launch(void* const* d_in, const int* in_sizes, int n_in,
                              void* d_out, int out_size) {
    const float* x  = (const float*)d_in[0];   // [B, L] fp32
    const float* tw = (const float*)d_in[1];   // [4] fp32
    float* out = (float*)d_out;

    const int L = 65536;
    const int B = in_sizes[0] / L;             // 64

    build_coeffs_kernel<<<1, THREADS>>>(tw);

    dim3 grid(L / TILE, B / 2);                // (32, 32)
    fir80_kernel<<<grid, THREADS>>>(x, out, L);
}

// round 2
// speedup vs baseline: 1.1405x; 1.1405x over previous
#include <cuda_runtime.h>
#include <math.h>

// ---------------------------------------------------------------------------
// HanningTemplateLayer == single 80-tap FIR:
//   out[b,j] = sum_{t=0..79} c[t] * x[b, j+t-40]   (zero padded)
//   c[t]     = sum_w softmax(tw)_w * hann_{2w}[(t-40)+w],  w in {10,20,30,40}
// Two batch rows packed per fma.rn.f32x2 lane.
// ---------------------------------------------------------------------------

#define THREADS 128
#define VOUT    8                  // outputs per thread (per row)
#define RING    10                 // window ring depth (VOUT + 2 prefetch)
#define CPRE    3                  // coeff prefetch depth (taps)
#define TILE    (THREADS * VOUT)   // 1024 columns per block
#define TAPS    80
#define HALF    40
#define SWZPAD  32                 // swizzle can bump index by up to 15

__device__ float2 g_c2[TAPS];      // combined filter, duplicated (c,c)

// XOR swizzle: keeps per-thread 64B-strided window reads conflict-free.
__device__ __forceinline__ int swz(int i) { return i ^ ((i >> 4) & 15); }

__global__ void build_coeffs_kernel(const float* __restrict__ tw) {
    int t = threadIdx.x;
    float w0 = tw[0], w1 = tw[1], w2 = tw[2], w3 = tw[3];
    float m  = fmaxf(fmaxf(w0, w1), fmaxf(w2, w3));
    float e0 = expf(w0 - m), e1 = expf(w1 - m), e2 = expf(w2 - m), e3 = expf(w3 - m);
    float s  = e0 + e1 + e2 + e3;
    float p[4] = { e0 / s, e1 / s, e2 / s, e3 / s };
    const int widths[4] = { 10, 20, 30, 40 };

    if (t < TAPS) {
        int d = t - HALF;                       // d in [-40, 39]
        double acc = 0.0;
        #pragma unroll
        for (int i = 0; i < 4; ++i) {
            int w = widths[i];
            int k = d + w;                      // index into hanning(2w)
            if (k >= 0 && k < 2 * w) {
                // np.hanning(M)[k] = 0.5 - 0.5*cos(2*pi*k/(M-1)), M = 2w
                double h = 0.5 - 0.5 * cos(2.0 * M_PI * (double)k / (double)(2 * w - 1));
                acc += (double)p[i] * h;
            }
        }
        float c = (float)acc;
        g_c2[t] = make_float2(c, c);
    }
}

__global__ __launch_bounds__(THREADS, 8)
void fir80_kernel(const float* __restrict__ x, float* __restrict__ out, int L) {
    __shared__ __align__(16) float2 sx[TILE + TAPS + SWZPAD]; // interleaved row pair
    __shared__ __align__(16) float2 sc[TAPS];

    const int rp   = blockIdx.y;            // row pair index (2 rows per block)
    const int col0 = blockIdx.x * TILE;     // first output column of this block
    const float* __restrict__ xa = x + (size_t)(2 * rp)     * L;
    const float* __restrict__ xb = x + (size_t)(2 * rp + 1) * L;

    // Cooperative tile load: shared index i <-> global column col0 - 40 + i
    #pragma unroll
    for (int k = 0; k < (TILE + TAPS + THREADS - 1) / THREADS; ++k) {
        int i = threadIdx.x + k * THREADS;
        if (i < TILE + TAPS) {
            int g = col0 - HALF + i;
            float a = 0.0f, b = 0.0f;
            if (g >= 0 && g < L) { a = xa[g]; b = xb[g]; }
            sx[swz(i)] = make_float2(a, b);
        }
    }
    if (threadIdx.x < TAPS) sc[threadIdx.x] = g_c2[threadIdx.x];
    __syncthreads();

    const unsigned long long* __restrict__ su =
        reinterpret_cast<const unsigned long long*>(sx);
    const unsigned long long* __restrict__ cu =
        reinterpret_cast<const unsigned long long*>(sc);

    const int lo = threadIdx.x * VOUT;      // shared index of (j0 - 40)

    unsigned long long acc[VOUT];
    unsigned long long win[RING];
    unsigned long long cbuf[CPRE];
    #pragma unroll
    for (int v = 0; v < VOUT; ++v) acc[v] = 0ull;
    #pragma unroll
    for (int v = 0; v < RING; ++v) win[v] = su[swz(lo + v)];
    #pragma unroll
    for (int v = 0; v < CPRE; ++v) cbuf[v] = cu[v];

    // Invariant at tap t: win[(t+i) % RING] holds sx[lo + t + i], i in [0, RING)
    //                     cbuf[(t+i) % CPRE] holds c[t+i],        i in [0, CPRE)
    #pragma unroll
    for (int t = 0; t < TAPS; ++t) {
        unsigned long long c2 = cbuf[t % CPRE];
        #pragma unroll
        for (int v = 0; v < VOUT; ++v) {
            asm("fma.rn.f32x2 %0, %1, %2, %0;"
                : "+l"(acc[v])
                : "l"(win[(t + v) % RING]), "l"(c2));
        }
        if (t < TAPS - CPRE)
            cbuf[t % CPRE] = cu[t + CPRE];
        if (t < TAPS - (RING - VOUT - 1))        // loads needed through t = 76
            win[t % RING] = su[swz(lo + t + RING)];
    }

    // Unpack and store: 8 consecutive floats per row -> 2x float4 per row
    float ra[VOUT], rb[VOUT];
    #pragma unroll
    for (int v = 0; v < VOUT; ++v) {
        float2 r;
        asm("mov.b64 {%0, %1}, %2;" : "=f"(r.x), "=f"(r.y) : "l"(acc[v]));
        ra[v] = r.x; rb[v] = r.y;
    }
    float* oa = out + (size_t)(2 * rp)     * L + col0 + lo;
    float* ob = out + (size_t)(2 * rp + 1) * L + col0 + lo;
    #pragma unroll
    for (int v = 0; v < VOUT; v += 4) {
        *reinterpret_cast<float4*>(oa + v) = make_float4(ra[v], ra[v+1], ra[v+2], ra[v+3]);
        *reinterpret_cast<float4*>(ob + v) = make_float4(rb[v], rb[v+1], rb[v+2], rb[v+3]);
    }
}

extern "C" void kernel_launch(void* const* d_in, const int* in_sizes, int n_in,
                              void* d_out, int out_size) {
    const float* x  = (const float*)d_in[0];   // [B, L] fp32
    const float* tw = (const float*)d_in[1];   // [4] fp32
    float* out = (float*)d_out;

    const int L = 65536;
    const int B = in_sizes[0] / L;             // 64

    build_coeffs_kernel<<<1, THREADS>>>(tw);

    dim3 grid(L / TILE, B / 2);                // (64, 32) = 2048 blocks
    fir80_kernel<<<grid, THREADS>>>(x, out, L);
}

// round 3
// speedup vs baseline: 1.5838x; 1.3887x over previous
#include <cuda_runtime.h>
#include <math.h>

// ---------------------------------------------------------------------------
// HanningTemplateLayer == single fused 80-tap FIR (coeffs computed in-block):
//   out[b,j] = sum_{t=0..79} c[t] * x[b, j+t-40]   (zero padded)
//   c[t]     = sum_w softmax(tw)_w * hann_{2w}[(t-40)+w],  w in {10,20,30,40}
// Two batch rows packed per fma.rn.f32x2 lane.
// Shared tile uses stride-9 padding (i -> i + (i>>3)): conflict-free strided
// window reads with pure immediate-offset LDS (no swizzle ALU).
// ---------------------------------------------------------------------------

#define THREADS 128
#define VOUT    8                  // outputs per thread (per row)
#define RING    12                 // window ring depth
#define TILE    (THREADS * VOUT)   // 1024 columns per block
#define TAPS    80
#define HALF    40
#define NLOG    (TILE + TAPS)      // 1104 logical float2 entries
#define NQUAD   (NLOG / 4)         // 276
#define NPHYS   (NLOG + NLOG / 8 + 8)

typedef unsigned long long ull;

__global__ __launch_bounds__(THREADS, 8)
void fir80_kernel(const float* __restrict__ x, const float* __restrict__ tw,
                  float* __restrict__ out, int L) {
    __shared__ __align__(16) float2 sx[NPHYS];   // padded, interleaved row pair
    __shared__ __align__(16) float2 sc[TAPS];    // (c,c) duplicated coeffs

    const int tid  = threadIdx.x;
    const int rp   = blockIdx.y;            // row pair index
    const int col0 = blockIdx.x * TILE;

    // ---- coefficients (threads 0..79), fp32 path -------------------------
    if (tid < TAPS) {
        float w0 = tw[0], w1 = tw[1], w2 = tw[2], w3 = tw[3];
        float m  = fmaxf(fmaxf(w0, w1), fmaxf(w2, w3));
        float e0 = expf(w0 - m), e1 = expf(w1 - m);
        float e2 = expf(w2 - m), e3 = expf(w3 - m);
        float s  = 1.0f / (e0 + e1 + e2 + e3);
        float p[4] = { e0 * s, e1 * s, e2 * s, e3 * s };
        const int widths[4] = { 10, 20, 30, 40 };
        int d = tid - HALF;
        float c = 0.0f;
        #pragma unroll
        for (int i = 0; i < 4; ++i) {
            int w = widths[i];
            int k = d + w;
            if (k >= 0 && k < 2 * w) {
                float h = 0.5f - 0.5f * cosf(6.283185307179586f * (float)k
                                             / (float)(2 * w - 1));
                c = fmaf(p[i], h, c);
            }
        }
        sc[tid] = make_float2(c, c);
    }

    // ---- tile fill: quads of 4 logical entries, LDG.128 ------------------
    const float* __restrict__ xa = x + (size_t)(2 * rp) * L;
    const float* __restrict__ xb = xa + L;
    #pragma unroll
    for (int it = 0; it < 3; ++it) {
        int q = tid + it * THREADS;
        if (q < NQUAD) {
            int i = q * 4;                    // logical index, 4-aligned
            int g = col0 - HALF + i;          // 4-aligned (40, L mult of 4)
            float4 a = make_float4(0.f, 0.f, 0.f, 0.f);
            float4 b = make_float4(0.f, 0.f, 0.f, 0.f);
            if (g >= 0 && g + 3 < L) {        // quads are fully in or out
                a = *reinterpret_cast<const float4*>(xa + g);
                b = *reinterpret_cast<const float4*>(xb + g);
            }
            int ph = i + (i >> 3);            // padded physical index
            sx[ph    ] = make_float2(a.x, b.x);
            sx[ph + 1] = make_float2(a.y, b.y);
            sx[ph + 2] = make_float2(a.z, b.z);
            sx[ph + 3] = make_float2(a.w, b.w);
        }
    }
    __syncthreads();

    // ---- 80-tap FIR, sliding register ring, immediate-offset LDS ---------
    const ull* __restrict__ P =
        reinterpret_cast<const ull*>(sx) + 9 * tid;      // thread window base
    const ulonglong2* __restrict__ scq =
        reinterpret_cast<const ulonglong2*>(sc);         // 2 taps per LDS.128

    ull acc[VOUT];
    ull win[RING];
    #pragma unroll
    for (int v = 0; v < VOUT; ++v) acc[v] = 0ull;
    #pragma unroll
    for (int j = 0; j < RING; ++j) win[j] = P[j + (j >> 3)];

    // Invariant at pair t: win[(t+i) % RING] == X[lo + t + i], i in [0, RING)
    #pragma unroll
    for (int t = 0; t < TAPS; t += 2) {
        ulonglong2 cq = scq[t >> 1];          // (c[t] dup, c[t+1] dup)
        #pragma unroll
        for (int v = 0; v < VOUT; ++v)
            asm("fma.rn.f32x2 %0, %1, %2, %0;"
                : "+l"(acc[v]) : "l"(win[(t + v) % RING]), "l"(cq.x));
        if (t + RING <= TAPS + VOUT - 2)      // entry t+12 needed thru 86
            win[t % RING] = P[(t + RING) + ((t + RING) >> 3)];
        #pragma unroll
        for (int v = 0; v < VOUT; ++v)
            asm("fma.rn.f32x2 %0, %1, %2, %0;"
                : "+l"(acc[v]) : "l"(win[(t + 1 + v) % RING]), "l"(cq.y));
        if (t + RING + 1 <= TAPS + VOUT - 2)
            win[(t + 1) % RING] = P[(t + RING + 1) + ((t + RING + 1) >> 3)];
    }

    // ---- unpack + store ---------------------------------------------------
    float ra[VOUT], rb[VOUT];
    #pragma unroll
    for (int v = 0; v < VOUT; ++v) {
        float2 r;
        asm("mov.b64 {%0, %1}, %2;" : "=f"(r.x), "=f"(r.y) : "l"(acc[v]));
        ra[v] = r.x; rb[v] = r.y;
    }
    float* oa = out + (size_t)(2 * rp)     * L + col0 + tid * VOUT;
    float* ob = out + (size_t)(2 * rp + 1) * L + col0 + tid * VOUT;
    #pragma unroll
    for (int v = 0; v < VOUT; v += 4) {
        *reinterpret_cast<float4*>(oa + v) =
            make_float4(ra[v], ra[v+1], ra[v+2], ra[v+3]);
        *reinterpret_cast<float4*>(ob + v) =
            make_float4(rb[v], rb[v+1], rb[v+2], rb[v+3]);
    }
}

extern "C" void kernel_launch(void* const* d_in, const int* in_sizes, int n_in,
                              void* d_out, int out_size) {
    const float* x  = (const float*)d_in[0];   // [B, L] fp32
    const float* tw = (const float*)d_in[1];   // [4] fp32
    float* out = (float*)d_out;

    const int L = 65536;
    const int B = in_sizes[0] / L;             // 64

    dim3 grid(L / TILE, B / 2);                // (64, 32) = 2048 blocks
    fir80_kernel<<<grid, THREADS>>>(x, tw, out, L);
}